// round 13
// baseline (speedup 1.0000x reference)
#include <cuda_runtime.h>

typedef unsigned long long u64;
typedef unsigned int u32;

#define NN 512
#define C 128
#define NROWS (NN * NN)
#define PLANE ((size_t)NROWS)
#define PLANE2 ((size_t)(NROWS / 2))

__device__ u32  g_wth[6 * 128 * 64];
__device__ u32  g_wtl[6 * 128 * 64];
__device__ u32  g_ah[(size_t)C * PLANE2];
__device__ u32  g_al[(size_t)C * PLANE2];
__device__ u32  g_bh[(size_t)C * PLANE2];
__device__ u32  g_bl[(size_t)C * PLANE2];
__device__ float g_go[(size_t)NROWS * C];
__device__ float g_kf[(size_t)C * NROWS];

__device__ __forceinline__ float sigm(float x) { return 1.0f / (1.0f + __expf(-x)); }
__device__ __forceinline__ u32 bf16x2(float hi_val, float lo_val) {
    u32 r; asm("cvt.rn.bf16x2.f32 %0, %1, %2;" : "=r"(r) : "f"(hi_val), "f"(lo_val)); return r;
}
__device__ __forceinline__ u32 smem_u32(const void* p) {
    u32 a; asm("{ .reg .u64 t; cvta.to.shared.u64 t, %1; cvt.u32.u64 %0, t; }" : "=r"(a) : "l"(p));
    return a;
}
__device__ __forceinline__ u32 sw128(u32 x) { return x ^ ((x >> 3) & 0x70); }

__device__ __forceinline__ void ldsm4(u32 addr, u32* r) {
    asm volatile("ldmatrix.sync.aligned.m8n8.x4.shared.b16 {%0,%1,%2,%3}, [%4];"
        : "=r"(r[0]), "=r"(r[1]), "=r"(r[2]), "=r"(r[3]) : "r"(addr));
}
__device__ __forceinline__ void mma_bf16(float* c, const u32* a, const u32* b) {
    asm volatile("mma.sync.aligned.m16n8k16.row.col.f32.bf16.bf16.f32 "
        "{%0,%1,%2,%3}, {%4,%5,%6,%7}, {%8,%9}, {%0,%1,%2,%3};"
        : "+f"(c[0]), "+f"(c[1]), "+f"(c[2]), "+f"(c[3])
        : "r"(a[0]), "r"(a[1]), "r"(a[2]), "r"(a[3]), "r"(b[0]), "r"(b[1]));
}
__device__ __forceinline__ void cpasync16(u32 dst, const void* src) {
    asm volatile("cp.async.cg.shared.global [%0], [%1], 16;" :: "r"(dst), "l"(src));
}

__device__ __forceinline__ int detect_mask_is_int32(const unsigned char* m) {
    const uint4* p = (const uint4*)m;
    unsigned acc = 0;
    #pragma unroll
    for (int i = 0; i < 4; i++) { uint4 v = p[i]; acc |= v.x | v.y | v.z | v.w; }
    return (acc & 0xFFFFFF00u) == 0u;
}
__device__ __forceinline__ float mask_val(const unsigned char* m, int row, int i32) {
    int v = i32 ? ((const int*)m)[row] : (int)m[row];
    return v ? 0.0f : 1.0f;
}

__device__ __forceinline__ void split2(float v0, float v1, u32& h, u32& l) {
    h = bf16x2(v1, v0);
    const float h0 = __uint_as_float(h << 16);
    const float h1 = __uint_as_float(h & 0xFFFF0000u);
    l = bf16x2(v1 - h1, v0 - h0);
}

// ============================================================================
__global__ __launch_bounds__(256)
void kW(const float* __restrict__ Wa, const float* __restrict__ Wga,
        const float* __restrict__ Wb, const float* __restrict__ Wgb,
        const float* __restrict__ Wgo, const float* __restrict__ Wo)
{
    const float* Ws[6] = {Wa, Wga, Wb, Wgb, Wgo, Wo};
    const float* W = Ws[blockIdx.x];
    for (int idx = threadIdx.x; idx < 128 * 64; idx += 256) {
        const int n = idx >> 6, k2 = idx & 63;
        u32 h, l;
        split2(W[(2 * k2) * 128 + n], W[(2 * k2 + 1) * 128 + n], h, l);
        g_wth[blockIdx.x * 8192 + n * 64 + k2] = h;
        g_wtl[blockIdx.x * 8192 + n * 64 + k2] = l;
    }
}

// ============================================================================
// kProjA: fused LN(z) + 5 projections (byte-identical to round 12 — known good)
// ============================================================================
#define KP_SMEM (96 * 1024)
__global__ __launch_bounds__(256, 2)
void kProjA(const float* __restrict__ z, const unsigned char* __restrict__ mask,
            const float* __restrict__ gin, const float* __restrict__ bin,
            const float* __restrict__ ba,  const float* __restrict__ bga,
            const float* __restrict__ bb,  const float* __restrict__ bgb,
            const float* __restrict__ bgo)
{
    extern __shared__ __align__(1024) char smem[];
    __shared__ float msk[64];
    const u32 sb = smem_u32(smem);
    const int tid = threadIdx.x;
    const int wid = tid >> 5, lane = tid & 31;
    const int nh = blockIdx.y;
    const int rowbase = blockIdx.x * 64;

    auto wload = [&](int mat, u32 boff) {
        #pragma unroll
        for (int s = 0; s < 8; s++) {
            const int id = tid + 256 * s;
            const int hilo = id >> 10;
            const int rem = id & 1023;
            const int n = rem >> 4, qq = rem & 15;
            const u32 dst = sb + boff + hilo * 16384
                          + (qq >> 3) * 8192 + sw128((u32)(n * 128 + (qq & 7) * 16));
            const u32* src = (hilo ? g_wtl : g_wth) + mat * 8192 + (nh * 64 + n) * 64 + qq * 4;
            cpasync16(dst, src);
        }
        asm volatile("cp.async.commit_group;" ::: "memory");
    };

    wload(0, 32768);
    wload(1, 65536);

    {
        const int lrow = tid >> 2, q = tid & 3;
        float v[32];
        const float* zr = z + (size_t)(rowbase + lrow) * C + q * 32;
        #pragma unroll
        for (int i = 0; i < 8; i++) *(float4*)(v + i * 4) = *(const float4*)(zr + i * 4);
        float s = 0.f, qsum = 0.f;
        #pragma unroll
        for (int i = 0; i < 32; i++) { s += v[i]; qsum += v[i] * v[i]; }
        s += __shfl_xor_sync(~0u, s, 1);  s += __shfl_xor_sync(~0u, s, 2);
        qsum += __shfl_xor_sync(~0u, qsum, 1);  qsum += __shfl_xor_sync(~0u, qsum, 2);
        const float mean = s * (1.0f / C);
        const float rstd = rsqrtf(qsum * (1.0f / C) - mean * mean + 1e-5f);
        #pragma unroll
        for (int i = 0; i < 16; i++) {
            const int c0 = q * 32 + 2 * i;
            const float x0 = (v[2*i]   - mean) * rstd * __ldg(gin + c0)     + __ldg(bin + c0);
            const float x1 = (v[2*i+1] - mean) * rstd * __ldg(gin + c0 + 1) + __ldg(bin + c0 + 1);
            u32 h, l; split2(x0, x1, h, l);
            const u32 off = (q >> 1) * 8192 + sw128((u32)(lrow * 128 + ((q & 1) * 16 + i) * 4));
            *(u32*)(smem + off) = h;
            *(u32*)(smem + 16384 + off) = l;
        }
    }
    if (tid < 64) {
        const int mi32 = detect_mask_is_int32(mask);
        msk[tid] = mask_val(mask, rowbase + tid, mi32);
    }
    __syncthreads();

    const u32 sAh = sb, sAl = sb + 16384;
    const u32 sB0h = sb + 32768, sB0l = sb + 32768 + 16384;
    const u32 sB1h = sb + 65536, sB1l = sb + 65536 + 16384;
    float* sT = (float*)(smem + 32768);

    const int wm = (wid & 3) * 16;
    const int wn = (wid >> 2) * 32;
    const int a_row = (lane & 7) + ((lane >> 3) & 1) * 8;
    const int a_kb  = (lane >> 4) * 8;
    const int b_row = (lane & 7) + (lane >> 4) * 8;
    const int b_kb  = ((lane >> 3) & 1) * 8;

    float accL[4][4], accG[4][4];

    #pragma unroll 1
    for (int t = 0; t < 2; t++) {
        asm volatile("cp.async.wait_group 0;" ::: "memory");
        __syncthreads();
        #pragma unroll
        for (int ni = 0; ni < 4; ni++)
            #pragma unroll
            for (int qk = 0; qk < 4; qk++) { accL[ni][qk] = 0.f; accG[ni][qk] = 0.f; }

        #pragma unroll
        for (int kf = 0; kf < 8; kf++) {
            const u32 hoff = (kf >> 2) * 8192;
            const int kp = (kf & 3) * 16;
            u32 Ah[4], Al[4], Bh[2][4], Bl[2][4];
            {
                const u32 o = hoff + sw128((u32)((wm + a_row) * 128 + (kp + a_kb) * 2));
                ldsm4(sAh + o, Ah);
                ldsm4(sAl + o, Al);
            }
            #pragma unroll
            for (int nb = 0; nb < 2; nb++) {
                const u32 o = hoff + sw128((u32)((wn + nb * 16 + b_row) * 128 + (kp + b_kb) * 2));
                ldsm4(sB0h + o, Bh[nb]);
                ldsm4(sB0l + o, Bl[nb]);
            }
            #pragma unroll
            for (int ni = 0; ni < 4; ni++) {
                const u32* bh = Bh[ni >> 1] + (ni & 1) * 2;
                const u32* bl = Bl[ni >> 1] + (ni & 1) * 2;
                mma_bf16(accL[ni], Ah, bh);
                mma_bf16(accL[ni], Ah, bl);
                mma_bf16(accL[ni], Al, bh);
            }
            #pragma unroll
            for (int nb = 0; nb < 2; nb++) {
                const u32 o = hoff + sw128((u32)((wn + nb * 16 + b_row) * 128 + (kp + b_kb) * 2));
                ldsm4(sB1h + o, Bh[nb]);
                ldsm4(sB1l + o, Bl[nb]);
            }
            #pragma unroll
            for (int ni = 0; ni < 4; ni++) {
                const u32* bh = Bh[ni >> 1] + (ni & 1) * 2;
                const u32* bl = Bl[ni >> 1] + (ni & 1) * 2;
                mma_bf16(accG[ni], Ah, bh);
                mma_bf16(accG[ni], Ah, bl);
                mma_bf16(accG[ni], Al, bh);
            }
        }
        __syncthreads();

        {
            const float* bl_ = t ? bb : ba;
            const float* bg_ = t ? bgb : bga;
            const int r0 = wm + (lane >> 2);
            const int r1 = r0 + 8;
            const float mv0 = msk[r0], mv1 = msk[r1];
            #pragma unroll
            for (int ni = 0; ni < 4; ni++) {
                const int c = wn + ni * 8 + (lane & 3) * 2;
                const int cg = nh * 64 + c;
                const float bl0 = __ldg(bl_ + cg), bl1 = __ldg(bl_ + cg + 1);
                const float bg0 = __ldg(bg_ + cg), bg1 = __ldg(bg_ + cg + 1);
                sT[c * 68 + r0]       = mv0 * sigm(accG[ni][0] + bg0) * (accL[ni][0] + bl0);
                sT[(c + 1) * 68 + r0] = mv0 * sigm(accG[ni][1] + bg1) * (accL[ni][1] + bl1);
                sT[c * 68 + r1]       = mv1 * sigm(accG[ni][2] + bg0) * (accL[ni][2] + bl0);
                sT[(c + 1) * 68 + r1] = mv1 * sigm(accG[ni][3] + bg1) * (accL[ni][3] + bl1);
            }
        }
        __syncthreads();
        {
            u32* ph = t ? g_bh : g_ah;
            u32* pl = t ? g_bl : g_al;
            const int c2 = tid >> 2;
            const int rb = (tid & 3) * 16;
            u32 hh[8], ll[8];
            #pragma unroll
            for (int j = 0; j < 4; j++) {
                float4 vv = *(float4*)(sT + c2 * 68 + rb + j * 4);
                split2(vv.x, vv.y, hh[2*j],   ll[2*j]);
                split2(vv.z, vv.w, hh[2*j+1], ll[2*j+1]);
            }
            const int c = nh * 64 + c2;
            const size_t p = (size_t)c * PLANE2 + (size_t)(rowbase + rb) / 2;
            *(uint4*)(ph + p)     = make_uint4(hh[0], hh[1], hh[2], hh[3]);
            *(uint4*)(ph + p + 4) = make_uint4(hh[4], hh[5], hh[6], hh[7]);
            *(uint4*)(pl + p)     = make_uint4(ll[0], ll[1], ll[2], ll[3]);
            *(uint4*)(pl + p + 4) = make_uint4(ll[4], ll[5], ll[6], ll[7]);
        }
        __syncthreads();

        if (t == 0) { wload(2, 32768); wload(3, 65536); }
        else        { wload(4, 32768); }
    }

    asm volatile("cp.async.wait_group 0;" ::: "memory");
    __syncthreads();
    #pragma unroll
    for (int ni = 0; ni < 4; ni++)
        #pragma unroll
        for (int qk = 0; qk < 4; qk++) accL[ni][qk] = 0.f;
    #pragma unroll
    for (int kf = 0; kf < 8; kf++) {
        const u32 hoff = (kf >> 2) * 8192;
        const int kp = (kf & 3) * 16;
        u32 Ah[4], Al[4], Bh[2][4], Bl[2][4];
        {
            const u32 o = hoff + sw128((u32)((wm + a_row) * 128 + (kp + a_kb) * 2));
            ldsm4(sAh + o, Ah);
            ldsm4(sAl + o, Al);
        }
        #pragma unroll
        for (int nb = 0; nb < 2; nb++) {
            const u32 o = hoff + sw128((u32)((wn + nb * 16 + b_row) * 128 + (kp + b_kb) * 2));
            ldsm4(sB0h + o, Bh[nb]);
            ldsm4(sB0l + o, Bl[nb]);
        }
        #pragma unroll
        for (int ni = 0; ni < 4; ni++) {
            const u32* bh = Bh[ni >> 1] + (ni & 1) * 2;
            const u32* bl = Bl[ni >> 1] + (ni & 1) * 2;
            mma_bf16(accL[ni], Ah, bh);
            mma_bf16(accL[ni], Ah, bl);
            mma_bf16(accL[ni], Al, bh);
        }
    }
    {
        const int r0 = wm + (lane >> 2);
        #pragma unroll
        for (int ni = 0; ni < 4; ni++) {
            const int cg = nh * 64 + wn + ni * 8 + (lane & 3) * 2;
            const float b0 = __ldg(bgo + cg), b1 = __ldg(bgo + cg + 1);
            *(float2*)(g_go + (size_t)(rowbase + r0) * C + cg)
                = make_float2(sigm(accL[ni][0] + b0), sigm(accL[ni][1] + b1));
            *(float2*)(g_go + (size_t)(rowbase + r0 + 8) * C + cg)
                = make_float2(sigm(accL[ni][2] + b0), sigm(accL[ni][3] + b1));
        }
    }
}

// ============================================================================
// Kernel B: 512 threads (16 warps, warp tile 32x32) for 2x latency cover.
// Same 3-stage cp.async pipeline and smem layout as round 12.
// ============================================================================
#define KB_STAGE (64 * 1024)
#define KB_SMEM (3 * KB_STAGE)

__global__ __launch_bounds__(512, 1)
void kB()
{
    extern __shared__ __align__(1024) char smem[];
    const u32 sb = smem_u32(smem);
    const int tid = threadIdx.x;
    const int wid = tid >> 5, lane = tid & 31;
    const int i0 = (blockIdx.x & 3) * 128;
    const int j0 = (blockIdx.x >> 2) * 128;
    const size_t ch = blockIdx.y;
    const u32* base0 = g_ah + ch * PLANE2 + (size_t)i0 * 256;
    const u32* base1 = g_al + ch * PLANE2 + (size_t)i0 * 256;
    const u32* base2 = g_bh + ch * PLANE2 + (size_t)j0 * 256;
    const u32* base3 = g_bl + ch * PLANE2 + (size_t)j0 * 256;

    const int wm = (wid & 3) * 32;    // 4 m-slots of 32 rows
    const int wn = (wid >> 2) * 32;   // 4 n-slots of 32 cols
    const int a_row = (lane & 7) + ((lane >> 3) & 1) * 8;
    const int a_kb  = (lane >> 4) * 8;
    const int b_row = (lane & 7) + (lane >> 4) * 8;
    const int b_kb  = ((lane >> 3) & 1) * 8;

    float acc[2][4][4];
    #pragma unroll
    for (int mi = 0; mi < 2; mi++)
        #pragma unroll
        for (int ni = 0; ni < 4; ni++)
            #pragma unroll
            for (int q = 0; q < 4; q++) acc[mi][ni][q] = 0.0f;

    auto issue = [&](int ck) {
        const u32 st = sb + (ck % 3) * KB_STAGE;
        const u32 k0h = (u32)ck * 32;
        #pragma unroll
        for (int m = 0; m < 8; m++) {
            const int id = tid + 512 * m;        // 0..4095
            const int tile = id >> 10;
            const int rem = id & 1023;
            const int row = rem >> 3, seg = rem & 7;
            const u32* src;
            if (tile == 0)      src = base0;
            else if (tile == 1) src = base1;
            else if (tile == 2) src = base2;
            else                src = base3;
            src += (size_t)row * 256 + k0h + seg * 4;
            const u32 dst = st + tile * 16384 + sw128((u32)(row * 128 + seg * 16));
            cpasync16(dst, src);
        }
        asm volatile("cp.async.commit_group;" ::: "memory");
    };

    issue(0);
    issue(1);

    #pragma unroll 1
    for (int ck = 0; ck < 8; ck++) {
        if (ck < 7) asm volatile("cp.async.wait_group 1;" ::: "memory");
        else        asm volatile("cp.async.wait_group 0;" ::: "memory");
        __syncthreads();
        const u32 st = sb + (ck % 3) * KB_STAGE;
        const u32 sAh = st, sAl = st + 16384, sBh = st + 32768, sBl = st + 49152;

        #pragma unroll
        for (int kf = 0; kf < 4; kf++) {
            u32 Ah[2][4], Al[2][4], Bh[2][4], Bl[2][4];
            #pragma unroll
            for (int mi = 0; mi < 2; mi++) {
                const u32 off = sw128((u32)((wm + mi * 16 + a_row) * 128 + (kf * 16 + a_kb) * 2));
                ldsm4(sAh + off, Ah[mi]);
                ldsm4(sAl + off, Al[mi]);
            }
            #pragma unroll
            for (int nb = 0; nb < 2; nb++) {
                const u32 off = sw128((u32)((wn + nb * 16 + b_row) * 128 + (kf * 16 + b_kb) * 2));
                ldsm4(sBh + off, Bh[nb]);
                ldsm4(sBl + off, Bl[nb]);
            }
            #pragma unroll
            for (int mi = 0; mi < 2; mi++)
                #pragma unroll
                for (int ni = 0; ni < 4; ni++) {
                    const u32* bh = Bh[ni >> 1] + (ni & 1) * 2;
                    const u32* bl = Bl[ni >> 1] + (ni & 1) * 2;
                    mma_bf16(acc[mi][ni], Ah[mi], bh);
                    mma_bf16(acc[mi][ni], Ah[mi], bl);
                    mma_bf16(acc[mi][ni], Al[mi], bh);
                }
        }
        __syncthreads();
        if (ck + 2 < 8) issue(ck + 2);
    }

    float* dst = g_kf + ch * PLANE;
    #pragma unroll
    for (int mi = 0; mi < 2; mi++) {
        const int rbase = i0 + wm + mi * 16 + (lane >> 2);
        #pragma unroll
        for (int ni = 0; ni < 4; ni++) {
            const int col = j0 + wn + ni * 8 + (lane & 3) * 2;
            *(float2*)(dst + (size_t)rbase * NN + col)
                = make_float2(acc[mi][ni][0], acc[mi][ni][1]);
            *(float2*)(dst + (size_t)(rbase + 8) * NN + col)
                = make_float2(acc[mi][ni][2], acc[mi][ni][3]);
        }
    }
}

// ============================================================================
// kOut: fused LN(k) + (@Wo + bo) * go -> out. M=64 x N=64 tiles, 2 CTAs/SM.
// grid (4096, 2), 256 threads. smem: kn [64][129] 33KB @0 | A 32KB @33792 |
// W-half 32KB @66560. Total 99328 B.
// ============================================================================
#define KO_A  33792
#define KO_W  66560
#define KO_SMEM (KO_W + 32768)
__global__ __launch_bounds__(256, 2)
void kOut(const float* __restrict__ go_, const float* __restrict__ bo_,
          const float* __restrict__ bo, float* __restrict__ out)
{
    extern __shared__ __align__(1024) char smem[];
    const u32 sb = smem_u32(smem);
    const int tid = threadIdx.x;
    const int wid = tid >> 5, lane = tid & 31;
    const int nh = blockIdx.y;
    const int rowbase = blockIdx.x * 64;
    float* kn = (float*)smem;   // [64 rows][129]

    // prefetch Wo N-half (mat 5)
    #pragma unroll
    for (int s = 0; s < 8; s++) {
        const int id = tid + 256 * s;
        const int hilo = id >> 10;
        const int rem = id & 1023;
        const int n = rem >> 4, qq = rem & 15;
        const u32 dst = sb + KO_W + hilo * 16384
                      + (qq >> 3) * 8192 + sw128((u32)(n * 128 + (qq & 7) * 16));
        const u32* src = (hilo ? g_wtl : g_wth) + 5 * 8192 + (nh * 64 + n) * 64 + qq * 4;
        cpasync16(dst, src);
    }
    asm volatile("cp.async.commit_group;" ::: "memory");

    // gather g_kf planes -> kn[row][c] (batched, MLP=8)
    {
        float4 vv[8];
        #pragma unroll
        for (int s = 0; s < 8; s++) {
            const int id = tid + 256 * s;        // 0..2047
            const int c = id >> 4, rf = id & 15; // c 0..127, rf*4 rows
            vv[s] = *(const float4*)(g_kf + (size_t)c * PLANE + rowbase + rf * 4);
        }
        #pragma unroll
        for (int s = 0; s < 8; s++) {
            const int id = tid + 256 * s;
            const int c = id >> 4, rf = id & 15;
            kn[(rf * 4 + 0) * 129 + c] = vv[s].x;
            kn[(rf * 4 + 1) * 129 + c] = vv[s].y;
            kn[(rf * 4 + 2) * 129 + c] = vv[s].z;
            kn[(rf * 4 + 3) * 129 + c] = vv[s].w;
        }
    }
    __syncthreads();

    // LN in registers -> A bf16 hi/lo
    {
        const int lrow = tid >> 2, q = tid & 3;
        float v[32];
        #pragma unroll
        for (int i = 0; i < 32; i++) v[i] = kn[lrow * 129 + q * 32 + i];
        float s = 0.f, qsum = 0.f;
        #pragma unroll
        for (int i = 0; i < 32; i++) { s += v[i]; qsum += v[i] * v[i]; }
        s += __shfl_xor_sync(~0u, s, 1);  s += __shfl_xor_sync(~0u, s, 2);
        qsum += __shfl_xor_sync(~0u, qsum, 1);  qsum += __shfl_xor_sync(~0u, qsum, 2);
        const float mean = s * (1.0f / C);
        const float rstd = rsqrtf(qsum * (1.0f / C) - mean * mean + 1e-5f);
        #pragma unroll
        for (int i = 0; i < 16; i++) {
            const int c0 = q * 32 + 2 * i;
            const float x0 = (v[2*i]   - mean) * rstd * __ldg(go_ + c0)     + __ldg(bo_ + c0);
            const float x1 = (v[2*i+1] - mean) * rstd * __ldg(go_ + c0 + 1) + __ldg(bo_ + c0 + 1);
            u32 h, l; split2(x0, x1, h, l);
            const u32 off = KO_A + (q >> 1) * 8192
                          + sw128((u32)(lrow * 128 + ((q & 1) * 16 + i) * 4));
            *(u32*)(smem + off) = h;
            *(u32*)(smem + 16384 + off) = l;
        }
    }
    __syncthreads();
    asm volatile("cp.async.wait_group 0;" ::: "memory");
    __syncthreads();

    const u32 sAh = sb + KO_A, sAl = sb + KO_A + 16384;
    const u32 sBh = sb + KO_W, sBl = sb + KO_W + 16384;
    const int wm = (wid & 3) * 16;
    const int wn = (wid >> 2) * 32;
    const int a_row = (lane & 7) + ((lane >> 3) & 1) * 8;
    const int a_kb  = (lane >> 4) * 8;
    const int b_row = (lane & 7) + (lane >> 4) * 8;
    const int b_kb  = ((lane >> 3) & 1) * 8;

    float accL[4][4];
    #pragma unroll
    for (int ni = 0; ni < 4; ni++)
        #pragma unroll
        for (int qk = 0; qk < 4; qk++) accL[ni][qk] = 0.f;

    #pragma unroll
    for (int kf = 0; kf < 8; kf++) {
        const u32 hoff = (kf >> 2) * 8192;
        const int kp = (kf & 3) * 16;
        u32 Ah[4], Al[4], Bh[2][4], Bl[2][4];
        {
            const u32 o = hoff + sw128((u32)((wm + a_row) * 128 + (kp + a_kb) * 2));
            ldsm4(sAh + o, Ah);
            ldsm4(sAl + o, Al);
        }
        #pragma unroll
        for (int nb = 0; nb < 2; nb++) {
            const u32 o = hoff + sw128((u32)((wn + nb * 16 + b_row) * 128 + (kp + b_kb) * 2));
            ldsm4(sBh + o, Bh[nb]);
            ldsm4(sBl + o, Bl[nb]);
        }
        #pragma unroll
        for (int ni = 0; ni < 4; ni++) {
            const u32* bh = Bh[ni >> 1] + (ni & 1) * 2;
            const u32* bl = Bl[ni >> 1] + (ni & 1) * 2;
            mma_bf16(accL[ni], Ah, bh);
            mma_bf16(accL[ni], Ah, bl);
            mma_bf16(accL[ni], Al, bh);
        }
    }

    {
        const int r0 = wm + (lane >> 2);
        #pragma unroll
        for (int ni = 0; ni < 4; ni++) {
            const int cg = nh * 64 + wn + ni * 8 + (lane & 3) * 2;
            const float b0 = __ldg(bo + cg), b1 = __ldg(bo + cg + 1);
            const size_t ro0 = (size_t)(rowbase + r0) * C + cg;
            const size_t ro1 = (size_t)(rowbase + r0 + 8) * C + cg;
            const float2 gg0 = *(const float2*)(g_go + ro0);
            const float2 gg1 = *(const float2*)(g_go + ro1);
            *(float2*)(out + ro0)
                = make_float2(gg0.x * (accL[ni][0] + b0), gg0.y * (accL[ni][1] + b1));
            *(float2*)(out + ro1)
                = make_float2(gg1.x * (accL[ni][2] + b0), gg1.y * (accL[ni][3] + b1));
        }
    }
}

// ============================================================================
extern "C" void kernel_launch(void* const* d_in, const int* in_sizes, int n_in,
                              void* d_out, int out_size)
{
    const float*         z    = (const float*)d_in[0];
    const unsigned char* mask = (const unsigned char*)d_in[1];
    const float* gin = (const float*)d_in[2],  *bin = (const float*)d_in[3];
    const float* Wa  = (const float*)d_in[4],  *ba  = (const float*)d_in[5];
    const float* Wga = (const float*)d_in[6],  *bga = (const float*)d_in[7];
    const float* Wb  = (const float*)d_in[8],  *bb  = (const float*)d_in[9];
    const float* Wgb = (const float*)d_in[10], *bgb = (const float*)d_in[11];
    const float* g_o = (const float*)d_in[12], *b_o = (const float*)d_in[13];
    const float* Wgo = (const float*)d_in[14], *bgo = (const float*)d_in[15];
    const float* Wo  = (const float*)d_in[16], *bo  = (const float*)d_in[17];
    float* out = (float*)d_out;

    static int attr_set = 0;
    if (!attr_set) {
        cudaFuncSetAttribute(kB, cudaFuncAttributeMaxDynamicSharedMemorySize, KB_SMEM);
        cudaFuncSetAttribute(kProjA, cudaFuncAttributeMaxDynamicSharedMemorySize, KP_SMEM);
        cudaFuncSetAttribute(kOut, cudaFuncAttributeMaxDynamicSharedMemorySize, KO_SMEM);
        attr_set = 1;
    }

    kW<<<6, 256>>>(Wa, Wga, Wb, Wgb, Wgo, Wo);
    kProjA<<<dim3(4096, 2), 256, KP_SMEM>>>(z, mask, gin, bin, ba, bga, bb, bgb, bgo);
    kB<<<dim3(16, C), 512, KB_SMEM>>>();
    kOut<<<dim3(4096, 2), 256, KO_SMEM>>>(g_o, b_o, bo, out);
}

// round 14
// speedup vs baseline: 1.1714x; 1.1714x over previous
#include <cuda_runtime.h>

typedef unsigned long long u64;
typedef unsigned int u32;

#define NN 512
#define C 128
#define NROWS (NN * NN)
#define PLANE ((size_t)NROWS)
#define PLANE2 ((size_t)(NROWS / 2))

__device__ u32  g_znh[(size_t)NROWS * 64];   // LN(z) hi bf16 pairs [row][64]
__device__ u32  g_znl[(size_t)NROWS * 64];
__device__ u32  g_wth[6 * 128 * 64];
__device__ u32  g_wtl[6 * 128 * 64];
__device__ u32  g_ah[(size_t)C * PLANE2];
__device__ u32  g_al[(size_t)C * PLANE2];
__device__ u32  g_bh[(size_t)C * PLANE2];
__device__ u32  g_bl[(size_t)C * PLANE2];
__device__ float g_go[(size_t)NROWS * C];
__device__ float g_kf[(size_t)C * NROWS];

__device__ __forceinline__ float sigm(float x) { return 1.0f / (1.0f + __expf(-x)); }
__device__ __forceinline__ u32 bf16x2(float hi_val, float lo_val) {
    u32 r; asm("cvt.rn.bf16x2.f32 %0, %1, %2;" : "=r"(r) : "f"(hi_val), "f"(lo_val)); return r;
}
__device__ __forceinline__ u32 smem_u32(const void* p) {
    u32 a; asm("{ .reg .u64 t; cvta.to.shared.u64 t, %1; cvt.u32.u64 %0, t; }" : "=r"(a) : "l"(p));
    return a;
}
__device__ __forceinline__ u32 sw128(u32 x) { return x ^ ((x >> 3) & 0x70); }

__device__ __forceinline__ void ldsm4(u32 addr, u32* r) {
    asm volatile("ldmatrix.sync.aligned.m8n8.x4.shared.b16 {%0,%1,%2,%3}, [%4];"
        : "=r"(r[0]), "=r"(r[1]), "=r"(r[2]), "=r"(r[3]) : "r"(addr));
}
__device__ __forceinline__ void mma_bf16(float* c, const u32* a, const u32* b) {
    asm volatile("mma.sync.aligned.m16n8k16.row.col.f32.bf16.bf16.f32 "
        "{%0,%1,%2,%3}, {%4,%5,%6,%7}, {%8,%9}, {%0,%1,%2,%3};"
        : "+f"(c[0]), "+f"(c[1]), "+f"(c[2]), "+f"(c[3])
        : "r"(a[0]), "r"(a[1]), "r"(a[2]), "r"(a[3]), "r"(b[0]), "r"(b[1]));
}
__device__ __forceinline__ void cpasync16(u32 dst, const void* src) {
    asm volatile("cp.async.cg.shared.global [%0], [%1], 16;" :: "r"(dst), "l"(src));
}

__device__ __forceinline__ int detect_mask_is_int32(const unsigned char* m) {
    const uint4* p = (const uint4*)m;
    unsigned acc = 0;
    #pragma unroll
    for (int i = 0; i < 4; i++) { uint4 v = p[i]; acc |= v.x | v.y | v.z | v.w; }
    return (acc & 0xFFFFFF00u) == 0u;
}
__device__ __forceinline__ float mask_val(const unsigned char* m, int row, int i32) {
    int v = i32 ? ((const int*)m)[row] : (int)m[row];
    return v ? 0.0f : 1.0f;
}

__device__ __forceinline__ void split2(float v0, float v1, u32& h, u32& l) {
    h = bf16x2(v1, v0);
    const float h0 = __uint_as_float(h << 16);
    const float h1 = __uint_as_float(h & 0xFFFF0000u);
    l = bf16x2(v1 - h1, v0 - h0);
}

// ============================================================================
__global__ __launch_bounds__(256)
void kW(const float* __restrict__ Wa, const float* __restrict__ Wga,
        const float* __restrict__ Wb, const float* __restrict__ Wgb,
        const float* __restrict__ Wgo, const float* __restrict__ Wo)
{
    const float* Ws[6] = {Wa, Wga, Wb, Wgb, Wgo, Wo};
    const float* W = Ws[blockIdx.x];
    for (int idx = threadIdx.x; idx < 128 * 64; idx += 256) {
        const int n = idx >> 6, k2 = idx & 63;
        u32 h, l;
        split2(W[(2 * k2) * 128 + n], W[(2 * k2 + 1) * 128 + n], h, l);
        g_wth[blockIdx.x * 8192 + n * 64 + k2] = h;
        g_wtl[blockIdx.x * 8192 + n * 64 + k2] = l;
    }
}

// ============================================================================
// kPrep: LN(z) -> bf16 hi/lo zn planes, row-major [row][64 u32]. (round-6 exact)
// ============================================================================
__global__ __launch_bounds__(256)
void kPrep(const float* __restrict__ z,
           const float* __restrict__ gin, const float* __restrict__ bin)
{
    const int tid = threadIdx.x;
    const int w = tid >> 5, lane = tid & 31;
    const int rowbase = blockIdx.x * 32;
    #pragma unroll
    for (int rr = 0; rr < 4; rr++) {
        const int row = rowbase + 4 * w + rr;
        float4 x = *(const float4*)(z + (size_t)row * C + lane * 4);
        float s = x.x + x.y + x.z + x.w;
        float q = x.x*x.x + x.y*x.y + x.z*x.z + x.w*x.w;
        #pragma unroll
        for (int o = 16; o; o >>= 1) {
            s += __shfl_xor_sync(~0u, s, o);
            q += __shfl_xor_sync(~0u, q, o);
        }
        const float mean = s * (1.0f / C);
        const float rstd = rsqrtf(q * (1.0f / C) - mean * mean + 1e-5f);
        float4 g4 = *(const float4*)(gin + lane * 4);
        float4 b4 = *(const float4*)(bin + lane * 4);
        const float v0 = (x.x - mean) * rstd * g4.x + b4.x;
        const float v1 = (x.y - mean) * rstd * g4.y + b4.y;
        const float v2 = (x.z - mean) * rstd * g4.z + b4.z;
        const float v3 = (x.w - mean) * rstd * g4.w + b4.w;
        u32 h0, l0, h1, l1;
        split2(v0, v1, h0, l0);
        split2(v2, v3, h1, l1);
        *(uint2*)(g_znh + (size_t)row * 64 + lane * 2) = make_uint2(h0, h1);
        *(uint2*)(g_znl + (size_t)row * 64 + lane * 2) = make_uint2(l0, l1);
    }
}

// ============================================================================
// kProj: pure pipelined GEMM. grid (4096 rowtiles, 2 N-halves, 3 jobs),
// 256 threads, 96KB -> 2 CTAs/SM.
//   job 0: a = mask*sigm(zn@Wga+bga)*(zn@Wa+ba) -> bf16 planes
//   job 1: b                                      -> bf16 planes
//   job 2: go = sigm(zn@Wgo+bgo)                  -> g_go
// smem: sA hi/lo 32K @0 | wb0 32K @32768 | wb1 32K @65536; sT aliases wb0.
// ============================================================================
#define KP_SMEM (96 * 1024)
__global__ __launch_bounds__(256, 2)
void kProj(const unsigned char* __restrict__ mask,
           const float* __restrict__ ba,  const float* __restrict__ bga,
           const float* __restrict__ bb,  const float* __restrict__ bgb,
           const float* __restrict__ bgo)
{
    extern __shared__ __align__(1024) char smem[];
    __shared__ float msk[64];
    const u32 sb = smem_u32(smem);
    const int tid = threadIdx.x;
    const int wid = tid >> 5, lane = tid & 31;
    const int nh = blockIdx.y;
    const int job = blockIdx.z;
    const int rowbase = blockIdx.x * 64;
    const int m0 = (job < 2) ? 2 * job : 4;

    // ---- A tile: zn bf16 hi/lo via cp.async (2048 x 16B) ----
    #pragma unroll
    for (int s = 0; s < 8; s++) {
        const int id = tid + 256 * s;          // 0..2047
        const int hilo = id >> 10;
        const int rem = id & 1023;
        const int row = rem >> 4, qq = rem & 15;
        const u32 dst = sb + hilo * 16384
                      + (qq >> 3) * 8192 + sw128((u32)(row * 128 + (qq & 7) * 16));
        const u32* src = (hilo ? g_znl : g_znh) + (size_t)(rowbase + row) * 64 + qq * 4;
        cpasync16(dst, src);
    }
    // ---- weight tiles ----
    auto wload = [&](int mat, u32 boff) {
        #pragma unroll
        for (int s = 0; s < 8; s++) {
            const int id = tid + 256 * s;
            const int hilo = id >> 10;
            const int rem = id & 1023;
            const int n = rem >> 4, qq = rem & 15;
            const u32 dst = sb + boff + hilo * 16384
                          + (qq >> 3) * 8192 + sw128((u32)(n * 128 + (qq & 7) * 16));
            const u32* src = (hilo ? g_wtl : g_wth) + mat * 8192 + (nh * 64 + n) * 64 + qq * 4;
            cpasync16(dst, src);
        }
    };
    wload(m0, 32768);
    if (job < 2) wload(m0 + 1, 65536);
    asm volatile("cp.async.commit_group;" ::: "memory");

    if (job < 2 && tid < 64) {
        const int mi32 = detect_mask_is_int32(mask);
        msk[tid] = mask_val(mask, rowbase + tid, mi32);
    }
    asm volatile("cp.async.wait_group 0;" ::: "memory");
    __syncthreads();

    const u32 sAh = sb, sAl = sb + 16384;
    const u32 sB0h = sb + 32768, sB0l = sb + 32768 + 16384;
    const u32 sB1h = sb + 65536, sB1l = sb + 65536 + 16384;
    float* sT = (float*)(smem + 32768);   // aliases wb0 after MMA

    const int wm = (wid & 3) * 16;
    const int wn = (wid >> 2) * 32;
    const int a_row = (lane & 7) + ((lane >> 3) & 1) * 8;
    const int a_kb  = (lane >> 4) * 8;
    const int b_row = (lane & 7) + (lane >> 4) * 8;
    const int b_kb  = ((lane >> 3) & 1) * 8;

    float accL[4][4], accG[4][4];
    #pragma unroll
    for (int ni = 0; ni < 4; ni++)
        #pragma unroll
        for (int qk = 0; qk < 4; qk++) { accL[ni][qk] = 0.f; accG[ni][qk] = 0.f; }

    if (job < 2) {
        #pragma unroll
        for (int kf = 0; kf < 8; kf++) {
            const u32 hoff = (kf >> 2) * 8192;
            const int kp = (kf & 3) * 16;
            u32 Ah[4], Al[4], Bh[2][4], Bl[2][4];
            {
                const u32 o = hoff + sw128((u32)((wm + a_row) * 128 + (kp + a_kb) * 2));
                ldsm4(sAh + o, Ah);
                ldsm4(sAl + o, Al);
            }
            #pragma unroll
            for (int nb = 0; nb < 2; nb++) {
                const u32 o = hoff + sw128((u32)((wn + nb * 16 + b_row) * 128 + (kp + b_kb) * 2));
                ldsm4(sB0h + o, Bh[nb]);
                ldsm4(sB0l + o, Bl[nb]);
            }
            #pragma unroll
            for (int ni = 0; ni < 4; ni++) {
                const u32* bh = Bh[ni >> 1] + (ni & 1) * 2;
                const u32* bl = Bl[ni >> 1] + (ni & 1) * 2;
                mma_bf16(accL[ni], Ah, bh);
                mma_bf16(accL[ni], Ah, bl);
                mma_bf16(accL[ni], Al, bh);
            }
            #pragma unroll
            for (int nb = 0; nb < 2; nb++) {
                const u32 o = hoff + sw128((u32)((wn + nb * 16 + b_row) * 128 + (kp + b_kb) * 2));
                ldsm4(sB1h + o, Bh[nb]);
                ldsm4(sB1l + o, Bl[nb]);
            }
            #pragma unroll
            for (int ni = 0; ni < 4; ni++) {
                const u32* bh = Bh[ni >> 1] + (ni & 1) * 2;
                const u32* bl = Bl[ni >> 1] + (ni & 1) * 2;
                mma_bf16(accG[ni], Ah, bh);
                mma_bf16(accG[ni], Ah, bl);
                mma_bf16(accG[ni], Al, bh);
            }
        }
        __syncthreads();

        // epilogue: gate + mask -> sT [c][row] -> bf16 planes
        {
            const float* bl_ = job ? bb : ba;
            const float* bg_ = job ? bgb : bga;
            const int r0 = wm + (lane >> 2);
            const int r1 = r0 + 8;
            const float mv0 = msk[r0], mv1 = msk[r1];
            #pragma unroll
            for (int ni = 0; ni < 4; ni++) {
                const int c = wn + ni * 8 + (lane & 3) * 2;
                const int cg = nh * 64 + c;
                const float bl0 = __ldg(bl_ + cg), bl1 = __ldg(bl_ + cg + 1);
                const float bg0 = __ldg(bg_ + cg), bg1 = __ldg(bg_ + cg + 1);
                sT[c * 68 + r0]       = mv0 * sigm(accG[ni][0] + bg0) * (accL[ni][0] + bl0);
                sT[(c + 1) * 68 + r0] = mv0 * sigm(accG[ni][1] + bg1) * (accL[ni][1] + bl1);
                sT[c * 68 + r1]       = mv1 * sigm(accG[ni][2] + bg0) * (accL[ni][2] + bl0);
                sT[(c + 1) * 68 + r1] = mv1 * sigm(accG[ni][3] + bg1) * (accL[ni][3] + bl1);
            }
        }
        __syncthreads();
        {
            u32* ph = job ? g_bh : g_ah;
            u32* pl = job ? g_bl : g_al;
            const int c2 = tid >> 2;
            const int rb = (tid & 3) * 16;
            u32 hh[8], ll[8];
            #pragma unroll
            for (int j = 0; j < 4; j++) {
                float4 vv = *(float4*)(sT + c2 * 68 + rb + j * 4);
                split2(vv.x, vv.y, hh[2*j],   ll[2*j]);
                split2(vv.z, vv.w, hh[2*j+1], ll[2*j+1]);
            }
            const int c = nh * 64 + c2;
            const size_t p = (size_t)c * PLANE2 + (size_t)(rowbase + rb) / 2;
            *(uint4*)(ph + p)     = make_uint4(hh[0], hh[1], hh[2], hh[3]);
            *(uint4*)(ph + p + 4) = make_uint4(hh[4], hh[5], hh[6], hh[7]);
            *(uint4*)(pl + p)     = make_uint4(ll[0], ll[1], ll[2], ll[3]);
            *(uint4*)(pl + p + 4) = make_uint4(ll[4], ll[5], ll[6], ll[7]);
        }
    } else {
        #pragma unroll
        for (int kf = 0; kf < 8; kf++) {
            const u32 hoff = (kf >> 2) * 8192;
            const int kp = (kf & 3) * 16;
            u32 Ah[4], Al[4], Bh[2][4], Bl[2][4];
            {
                const u32 o = hoff + sw128((u32)((wm + a_row) * 128 + (kp + a_kb) * 2));
                ldsm4(sAh + o, Ah);
                ldsm4(sAl + o, Al);
            }
            #pragma unroll
            for (int nb = 0; nb < 2; nb++) {
                const u32 o = hoff + sw128((u32)((wn + nb * 16 + b_row) * 128 + (kp + b_kb) * 2));
                ldsm4(sB0h + o, Bh[nb]);
                ldsm4(sB0l + o, Bl[nb]);
            }
            #pragma unroll
            for (int ni = 0; ni < 4; ni++) {
                const u32* bh = Bh[ni >> 1] + (ni & 1) * 2;
                const u32* bl = Bl[ni >> 1] + (ni & 1) * 2;
                mma_bf16(accL[ni], Ah, bh);
                mma_bf16(accL[ni], Ah, bl);
                mma_bf16(accL[ni], Al, bh);
            }
        }
        const int r0 = wm + (lane >> 2);
        #pragma unroll
        for (int ni = 0; ni < 4; ni++) {
            const int cg = nh * 64 + wn + ni * 8 + (lane & 3) * 2;
            const float b0 = __ldg(bgo + cg), b1 = __ldg(bgo + cg + 1);
            *(float2*)(g_go + (size_t)(rowbase + r0) * C + cg)
                = make_float2(sigm(accL[ni][0] + b0), sigm(accL[ni][1] + b1));
            *(float2*)(g_go + (size_t)(rowbase + r0 + 8) * C + cg)
                = make_float2(sigm(accL[ni][2] + b0), sigm(accL[ni][3] + b1));
        }
    }
}

// ============================================================================
// Kernel B (round-12 exact, 256 threads — known good 256 us)
// ============================================================================
#define KB_STAGE (64 * 1024)
#define KB_SMEM (3 * KB_STAGE)

__global__ __launch_bounds__(256, 1)
void kB()
{
    extern __shared__ __align__(1024) char smem[];
    const u32 sb = smem_u32(smem);
    const int tid = threadIdx.x;
    const int wid = tid >> 5, lane = tid & 31;
    const int i0 = (blockIdx.x & 3) * 128;
    const int j0 = (blockIdx.x >> 2) * 128;
    const size_t ch = blockIdx.y;
    const u32* base0 = g_ah + ch * PLANE2 + (size_t)i0 * 256;
    const u32* base1 = g_al + ch * PLANE2 + (size_t)i0 * 256;
    const u32* base2 = g_bh + ch * PLANE2 + (size_t)j0 * 256;
    const u32* base3 = g_bl + ch * PLANE2 + (size_t)j0 * 256;

    const int wm = (wid & 1) * 64;
    const int wn = (wid >> 1) * 32;
    const int a_row = (lane & 7) + ((lane >> 3) & 1) * 8;
    const int a_kb  = (lane >> 4) * 8;
    const int b_row = (lane & 7) + (lane >> 4) * 8;
    const int b_kb  = ((lane >> 3) & 1) * 8;

    float acc[4][4][4];
    #pragma unroll
    for (int mi = 0; mi < 4; mi++)
        #pragma unroll
        for (int ni = 0; ni < 4; ni++)
            #pragma unroll
            for (int q = 0; q < 4; q++) acc[mi][ni][q] = 0.0f;

    auto issue = [&](int ck) {
        const u32 st = sb + (ck % 3) * KB_STAGE;
        const u32 k0h = (u32)ck * 32;
        #pragma unroll
        for (int m = 0; m < 16; m++) {
            const int id = tid + 256 * m;
            const int tile = id >> 10;
            const int rem = id & 1023;
            const int row = rem >> 3, seg = rem & 7;
            const u32* src;
            if (tile == 0)      src = base0;
            else if (tile == 1) src = base1;
            else if (tile == 2) src = base2;
            else                src = base3;
            src += (size_t)row * 256 + k0h + seg * 4;
            const u32 dst = st + tile * 16384 + sw128((u32)(row * 128 + seg * 16));
            cpasync16(dst, src);
        }
        asm volatile("cp.async.commit_group;" ::: "memory");
    };

    issue(0);
    issue(1);

    #pragma unroll 1
    for (int ck = 0; ck < 8; ck++) {
        if (ck < 7) asm volatile("cp.async.wait_group 1;" ::: "memory");
        else        asm volatile("cp.async.wait_group 0;" ::: "memory");
        __syncthreads();
        const u32 st = sb + (ck % 3) * KB_STAGE;
        const u32 sAh = st, sAl = st + 16384, sBh = st + 32768, sBl = st + 49152;

        #pragma unroll
        for (int kf = 0; kf < 4; kf++) {
            u32 Ah[4][4], Al[4][4], Bh[2][4], Bl[2][4];
            #pragma unroll
            for (int mi = 0; mi < 4; mi++) {
                const u32 off = sw128((u32)((wm + mi * 16 + a_row) * 128 + (kf * 16 + a_kb) * 2));
                ldsm4(sAh + off, Ah[mi]);
                ldsm4(sAl + off, Al[mi]);
            }
            #pragma unroll
            for (int nb = 0; nb < 2; nb++) {
                const u32 off = sw128((u32)((wn + nb * 16 + b_row) * 128 + (kf * 16 + b_kb) * 2));
                ldsm4(sBh + off, Bh[nb]);
                ldsm4(sBl + off, Bl[nb]);
            }
            #pragma unroll
            for (int mi = 0; mi < 4; mi++)
                #pragma unroll
                for (int ni = 0; ni < 4; ni++) {
                    const u32* bh = Bh[ni >> 1] + (ni & 1) * 2;
                    const u32* bl = Bl[ni >> 1] + (ni & 1) * 2;
                    mma_bf16(acc[mi][ni], Ah[mi], bh);
                    mma_bf16(acc[mi][ni], Ah[mi], bl);
                    mma_bf16(acc[mi][ni], Al[mi], bh);
                }
        }
        __syncthreads();
        if (ck + 2 < 8) issue(ck + 2);
    }

    float* dst = g_kf + ch * PLANE;
    #pragma unroll
    for (int mi = 0; mi < 4; mi++) {
        const int rbase = i0 + wm + mi * 16 + (lane >> 2);
        #pragma unroll
        for (int ni = 0; ni < 4; ni++) {
            const int col = j0 + wn + ni * 8 + (lane & 3) * 2;
            *(float2*)(dst + (size_t)rbase * NN + col)
                = make_float2(acc[mi][ni][0], acc[mi][ni][1]);
            *(float2*)(dst + (size_t)(rbase + 8) * NN + col)
                = make_float2(acc[mi][ni][2], acc[mi][ni][3]);
        }
    }
}

// ============================================================================
// kOut (round-12 exact — known good 194 us)
// ============================================================================
#define KO_A  66048
#define KO_W  131584
#define KO_SMEM (KO_W + 65536)
__global__ __launch_bounds__(512, 1)
void kOut(const float* __restrict__ go_, const float* __restrict__ bo_,
          const float* __restrict__ bo, float* __restrict__ out)
{
    extern __shared__ __align__(1024) char smem[];
    const u32 sb = smem_u32(smem);
    const int tid = threadIdx.x;
    const int wid = tid >> 5, lane = tid & 31;
    const int rowbase = blockIdx.x * 128;
    float* kn = (float*)smem;

    #pragma unroll
    for (int s = 0; s < 8; s++) {
        const int id = tid + 512 * s;
        const int hilo = id >> 11;
        const int rem = id & 2047;
        const int n = rem >> 4, qq = rem & 15;
        const u32 dst = sb + KO_W + hilo * 32768
                      + (qq >> 3) * 16384 + sw128((u32)(n * 128 + (qq & 7) * 16));
        const u32* src = (hilo ? g_wtl : g_wth) + 5 * 8192 + n * 64 + qq * 4;
        cpasync16(dst, src);
    }
    asm volatile("cp.async.commit_group;" ::: "memory");

    {
        float4 vv[8];
        #pragma unroll
        for (int s = 0; s < 8; s++) {
            const int id = tid + 512 * s;
            const int c = id >> 5, rf = id & 31;
            vv[s] = *(const float4*)(g_kf + (size_t)c * PLANE + rowbase + rf * 4);
        }
        #pragma unroll
        for (int s = 0; s < 8; s++) {
            const int id = tid + 512 * s;
            const int c = id >> 5, rf = id & 31;
            kn[(rf * 4 + 0) * 129 + c] = vv[s].x;
            kn[(rf * 4 + 1) * 129 + c] = vv[s].y;
            kn[(rf * 4 + 2) * 129 + c] = vv[s].z;
            kn[(rf * 4 + 3) * 129 + c] = vv[s].w;
        }
    }
    __syncthreads();

    {
        const int lrow = tid >> 2, q = tid & 3;
        float v[32];
        #pragma unroll
        for (int i = 0; i < 32; i++) v[i] = kn[lrow * 129 + q * 32 + i];
        float s = 0.f, qsum = 0.f;
        #pragma unroll
        for (int i = 0; i < 32; i++) { s += v[i]; qsum += v[i] * v[i]; }
        s += __shfl_xor_sync(~0u, s, 1);  s += __shfl_xor_sync(~0u, s, 2);
        qsum += __shfl_xor_sync(~0u, qsum, 1);  qsum += __shfl_xor_sync(~0u, qsum, 2);
        const float mean = s * (1.0f / C);
        const float rstd = rsqrtf(qsum * (1.0f / C) - mean * mean + 1e-5f);
        #pragma unroll
        for (int i = 0; i < 16; i++) {
            const int c0 = q * 32 + 2 * i;
            const float x0 = (v[2*i]   - mean) * rstd * __ldg(go_ + c0)     + __ldg(bo_ + c0);
            const float x1 = (v[2*i+1] - mean) * rstd * __ldg(go_ + c0 + 1) + __ldg(bo_ + c0 + 1);
            u32 h, l; split2(x0, x1, h, l);
            const u32 off = KO_A + (q >> 1) * 16384
                          + sw128((u32)(lrow * 128 + ((q & 1) * 16 + i) * 4));
            *(u32*)(smem + off) = h;
            *(u32*)(smem + 32768 + off) = l;
        }
    }
    __syncthreads();
    asm volatile("cp.async.wait_group 0;" ::: "memory");
    __syncthreads();

    const u32 sAh = sb + KO_A, sAl = sb + KO_A + 32768;
    const u32 sBh = sb + KO_W, sBl = sb + KO_W + 32768;
    const int wm = (wid & 3) * 32;
    const int wn = (wid >> 2) * 32;
    const int a_row = (lane & 7) + ((lane >> 3) & 1) * 8;
    const int a_kb  = (lane >> 4) * 8;
    const int b_row = (lane & 7) + (lane >> 4) * 8;
    const int b_kb  = ((lane >> 3) & 1) * 8;

    float accL[2][4][4];
    #pragma unroll
    for (int mi = 0; mi < 2; mi++)
        #pragma unroll
        for (int ni = 0; ni < 4; ni++)
            #pragma unroll
            for (int qk = 0; qk < 4; qk++) accL[mi][ni][qk] = 0.f;

    #pragma unroll
    for (int kf = 0; kf < 8; kf++) {
        const u32 hoff = (kf >> 2) * 16384;
        const int kp = (kf & 3) * 16;
        u32 Ah[2][4], Al[2][4], Bh[2][4], Bl[2][4];
        #pragma unroll
        for (int mi = 0; mi < 2; mi++) {
            const u32 o = hoff + sw128((u32)((wm + mi * 16 + a_row) * 128 + (kp + a_kb) * 2));
            ldsm4(sAh + o, Ah[mi]);
            ldsm4(sAl + o, Al[mi]);
        }
        #pragma unroll
        for (int nb = 0; nb < 2; nb++) {
            const u32 o = hoff + sw128((u32)((wn + nb * 16 + b_row) * 128 + (kp + b_kb) * 2));
            ldsm4(sBh + o, Bh[nb]);
            ldsm4(sBl + o, Bl[nb]);
        }
        #pragma unroll
        for (int mi = 0; mi < 2; mi++)
            #pragma unroll
            for (int ni = 0; ni < 4; ni++) {
                const u32* bh = Bh[ni >> 1] + (ni & 1) * 2;
                const u32* bl = Bl[ni >> 1] + (ni & 1) * 2;
                mma_bf16(accL[mi][ni], Ah[mi], bh);
                mma_bf16(accL[mi][ni], Ah[mi], bl);
                mma_bf16(accL[mi][ni], Al[mi], bh);
            }
    }

    #pragma unroll
    for (int mi = 0; mi < 2; mi++) {
        const int r0 = wm + mi * 16 + (lane >> 2);
        #pragma unroll
        for (int ni = 0; ni < 4; ni++) {
            const int c = wn + ni * 8 + (lane & 3) * 2;
            const float b0 = __ldg(bo + c), b1 = __ldg(bo + c + 1);
            const size_t ro0 = (size_t)(rowbase + r0) * C + c;
            const size_t ro1 = (size_t)(rowbase + r0 + 8) * C + c;
            const float2 gg0 = *(const float2*)(g_go + ro0);
            const float2 gg1 = *(const float2*)(g_go + ro1);
            *(float2*)(out + ro0)
                = make_float2(gg0.x * (accL[mi][ni][0] + b0), gg0.y * (accL[mi][ni][1] + b1));
            *(float2*)(out + ro1)
                = make_float2(gg1.x * (accL[mi][ni][2] + b0), gg1.y * (accL[mi][ni][3] + b1));
        }
    }
}

// ============================================================================
extern "C" void kernel_launch(void* const* d_in, const int* in_sizes, int n_in,
                              void* d_out, int out_size)
{
    const float*         z    = (const float*)d_in[0];
    const unsigned char* mask = (const unsigned char*)d_in[1];
    const float* gin = (const float*)d_in[2],  *bin = (const float*)d_in[3];
    const float* Wa  = (const float*)d_in[4],  *ba  = (const float*)d_in[5];
    const float* Wga = (const float*)d_in[6],  *bga = (const float*)d_in[7];
    const float* Wb  = (const float*)d_in[8],  *bb  = (const float*)d_in[9];
    const float* Wgb = (const float*)d_in[10], *bgb = (const float*)d_in[11];
    const float* g_o = (const float*)d_in[12], *b_o = (const float*)d_in[13];
    const float* Wgo = (const float*)d_in[14], *bgo = (const float*)d_in[15];
    const float* Wo  = (const float*)d_in[16], *bo  = (const float*)d_in[17];
    float* out = (float*)d_out;

    static int attr_set = 0;
    if (!attr_set) {
        cudaFuncSetAttribute(kB, cudaFuncAttributeMaxDynamicSharedMemorySize, KB_SMEM);
        cudaFuncSetAttribute(kProj, cudaFuncAttributeMaxDynamicSharedMemorySize, KP_SMEM);
        cudaFuncSetAttribute(kOut, cudaFuncAttributeMaxDynamicSharedMemorySize, KO_SMEM);
        attr_set = 1;
    }

    kW<<<6, 256>>>(Wa, Wga, Wb, Wgb, Wgo, Wo);
    kPrep<<<NROWS / 32, 256>>>(z, gin, bin);
    kProj<<<dim3(4096, 2, 3), 256, KP_SMEM>>>(mask, ba, bga, bb, bgb, bgo);
    kB<<<dim3(16, C), 256, KB_SMEM>>>();
    kOut<<<2048, 512, KO_SMEM>>>(g_o, b_o, bo, out);
}